// round 15
// baseline (speedup 1.0000x reference)
#include <cuda_runtime.h>

// NeRF volume rendering compositing — round 15: pre-scan rgb accumulation.
// Base = round-13 best (12.58us). Key algebra: w_i = Tl * w_local_i where
// w_local_i depends only on this lane's sigma/dists. So each lane folds its
// rgb into LOCAL partials (cR,cG,cB,cW) BEFORE the segment scan — the rgb
// loads are scan-independent (one latency exposure per round, batched with
// sigma/dists) and the 12 rgb registers die before the scan; only 4
// partials cross it. Lanes 0..11 (samples 0..47) do this unconditionally
// (they are active ~always; termination depth 36.8 +/- 5.3 samples) —
// also strictly MORE accurate than thresholded skipping. Lanes 12..15 keep
// the exact scan-predicated path (~2% of segments). Tail rounds unchanged.
// Inputs (metadata order):
//   d_in[0]: sigma  [B, S]    float32   (B=65536, S=512)
//   d_in[1]: dists  [B, S]    float32
//   d_in[2]: rgb    [B, S, 3] float32
//   d_in[3]: bg_col [3]       float32
// Output: rgb_map [B, 3] float32
//
//   x = sigma*dists*25; alpha = 1-exp(-x); T = excl cumprod(exp(-x)+1e-10)
//   w = alpha*T; out_c = sum w*clip(rgb,0,1) + (1-sum w)*bg_c
// Truncation only past sample 48 at T < 1e-4 -> abs err < 1e-4,
// expected rel_err ~1.3e-5 (R7/R11 signature).

#define DIST_SCALE 25.0f
#define T_THRESH   1e-4f
#define FULLMASK   0xffffffffu
#define SEGW       16
#define SPECL      12   // lanes with unconditional pre-scan rgb accumulation

__device__ __forceinline__ float clip01(float v) {
    return fminf(fmaxf(v, 0.0f), 1.0f);
}

__global__ __launch_bounds__(128, 14)
void nerf_composite_kernel(const float4* __restrict__ sigma4,
                           const float4* __restrict__ dists4,
                           const float4* __restrict__ rgb4,
                           const float*  __restrict__ bg,
                           float*        __restrict__ out,
                           int B)
{
    const int warp  = (int)((blockIdx.x * (unsigned)blockDim.x + threadIdx.x) >> 5);
    const int lane  = threadIdx.x & 31;
    const int slane = lane & (SEGW - 1);
    const int ray   = warp * 2 + (lane >> 4);
    if (ray >= B) return;

    float accW = 0.0f, accR = 0.0f, accG = 0.0f, accB = 0.0f;

    // ================= Round 0 (peeled): samples 0..63 =================
    const int  idx0  = ray * 128 + slane;
    const int  ridx0 = ray * 384 + slane * 3;
    const bool specl = (slane < SPECL);

    const float4 sg = sigma4[idx0];
    const float4 dt = dists4[idx0];
    float4 q0, q1, q2;
    if (specl) {                      // scan-independent: batched with sg/dt
        q0 = rgb4[ridx0 + 0];
        q1 = rgb4[ridx0 + 1];
        q2 = rgb4[ridx0 + 2];
    }

    // Local transmittance factors and weights (pre-scan)
    const float f0 = __expf(-DIST_SCALE * sg.x * dt.x);
    const float f1 = __expf(-DIST_SCALE * sg.y * dt.y);
    const float f2 = __expf(-DIST_SCALE * sg.z * dt.z);
    const float f3 = __expf(-DIST_SCALE * sg.w * dt.w);
    const float g0 = f0 + 1e-10f, g1 = f1 + 1e-10f;
    const float g2 = f2 + 1e-10f, g3 = f3 + 1e-10f;

    float w0 = (1.0f - f0);
    float t  = g0;
    float w1 = (1.0f - f1) * t;  t *= g1;
    float w2 = (1.0f - f2) * t;  t *= g2;
    float w3 = (1.0f - f3) * t;
    const float p = t * g3;

    // Pre-scan rgb fold: q registers die here.
    float cR = 0.0f, cG = 0.0f, cB = 0.0f, cW = 0.0f;
    if (specl) {
        cR = w0 * clip01(q0.x) + w1 * clip01(q0.w)
           + w2 * clip01(q1.z) + w3 * clip01(q2.y);
        cG = w0 * clip01(q0.y) + w1 * clip01(q1.x)
           + w2 * clip01(q1.w) + w3 * clip01(q2.z);
        cB = w0 * clip01(q0.z) + w1 * clip01(q1.y)
           + w2 * clip01(q2.x) + w3 * clip01(q2.w);
        cW = w0 + w1 + w2 + w3;
    }

    // Segment scan (width 16)
    float incl = p;
    #pragma unroll
    for (int off = 1; off < SEGW; off <<= 1) {
        const float v = __shfl_up_sync(FULLMASK, incl, off, SEGW);
        if (slane >= off) incl *= v;
    }
    float excl = __shfl_up_sync(FULLMASK, incl, 1, SEGW);
    if (slane == 0) excl = 1.0f;
    float T_run = __shfl_sync(FULLMASK, incl, SEGW - 1, SEGW);
    const float Tl0 = excl;           // round-0: T_run starts at 1

    if (specl) {                       // post-scan: 4 FMAs
        accR += Tl0 * cR;  accG += Tl0 * cG;
        accB += Tl0 * cB;  accW += Tl0 * cW;
    } else if (Tl0 >= T_THRESH) {      // rare tail lanes 12..15 (~2% of segs)
        const float4 a0 = rgb4[ridx0 + 0];
        const float4 a1 = rgb4[ridx0 + 1];
        const float4 a2 = rgb4[ridx0 + 2];
        const float v0 = w0 * Tl0, v1 = w1 * Tl0, v2 = w2 * Tl0, v3 = w3 * Tl0;
        accR += v0 * clip01(a0.x) + v1 * clip01(a0.w)
              + v2 * clip01(a1.z) + v3 * clip01(a2.y);
        accG += v0 * clip01(a0.y) + v1 * clip01(a1.x)
              + v2 * clip01(a1.w) + v3 * clip01(a2.z);
        accB += v0 * clip01(a0.z) + v1 * clip01(a1.y)
              + v2 * clip01(a2.x) + v3 * clip01(a2.w);
        accW += v0 + v1 + v2 + v3;
    }

    // ================= Rounds 1..7: rare (~0.02% of segments) ============
    if (!__all_sync(FULLMASK, T_run < T_THRESH)) {
        #pragma unroll 1
        for (int k = 1; k < 8; ++k) {
            const int idx = ray * 128 + k * 16 + slane;
            const float4 sgk = sigma4[idx];
            const float4 dtk = dists4[idx];

            const float e0 = __expf(-DIST_SCALE * sgk.x * dtk.x);
            const float e1 = __expf(-DIST_SCALE * sgk.y * dtk.y);
            const float e2 = __expf(-DIST_SCALE * sgk.z * dtk.z);
            const float e3 = __expf(-DIST_SCALE * sgk.w * dtk.w);
            const float h0 = e0 + 1e-10f, h1 = e1 + 1e-10f;
            const float h2 = e2 + 1e-10f, h3 = e3 + 1e-10f;

            float u0 = (1.0f - e0);
            float tt = h0;
            float u1 = (1.0f - e1) * tt;  tt *= h1;
            float u2 = (1.0f - e2) * tt;  tt *= h2;
            float u3 = (1.0f - e3) * tt;
            const float pk = tt * h3;

            float inclk = pk;
            #pragma unroll
            for (int off = 1; off < SEGW; off <<= 1) {
                const float v = __shfl_up_sync(FULLMASK, inclk, off, SEGW);
                if (slane >= off) inclk *= v;
            }
            float exclk = __shfl_up_sync(FULLMASK, inclk, 1, SEGW);
            if (slane == 0) exclk = 1.0f;
            const float totalk = __shfl_sync(FULLMASK, inclk, SEGW - 1, SEGW);
            const float Tl = T_run * exclk;

            if (Tl >= T_THRESH) {
                const int ridx = ray * 384 + k * 48 + slane * 3;
                const float4 a0 = rgb4[ridx + 0];
                const float4 a1 = rgb4[ridx + 1];
                const float4 a2 = rgb4[ridx + 2];
                const float v0 = u0 * Tl, v1 = u1 * Tl, v2 = u2 * Tl, v3 = u3 * Tl;
                accR += v0 * clip01(a0.x) + v1 * clip01(a0.w)
                      + v2 * clip01(a1.z) + v3 * clip01(a2.y);
                accG += v0 * clip01(a0.y) + v1 * clip01(a1.x)
                      + v2 * clip01(a1.w) + v3 * clip01(a2.z);
                accB += v0 * clip01(a0.z) + v1 * clip01(a1.y)
                      + v2 * clip01(a2.x) + v3 * clip01(a2.w);
                accW += v0 + v1 + v2 + v3;
            }

            T_run *= totalk;
            if (__all_sync(FULLMASK, T_run < T_THRESH)) break;
        }
    }

    // ================= Segment reduction + output =======================
    #pragma unroll
    for (int off = SEGW / 2; off >= 1; off >>= 1) {
        accW += __shfl_down_sync(FULLMASK, accW, off, SEGW);
        accR += __shfl_down_sync(FULLMASK, accR, off, SEGW);
        accG += __shfl_down_sync(FULLMASK, accG, off, SEGW);
        accB += __shfl_down_sync(FULLMASK, accB, off, SEGW);
    }

    if (slane == 0) {
        const float rem = 1.0f - accW;
        out[ray * 3 + 0] = accR + rem * __ldg(&bg[0]);
        out[ray * 3 + 1] = accG + rem * __ldg(&bg[1]);
        out[ray * 3 + 2] = accB + rem * __ldg(&bg[2]);
    }
}

extern "C" void kernel_launch(void* const* d_in, const int* in_sizes, int n_in,
                              void* d_out, int out_size)
{
    const float4* sigma4 = (const float4*)d_in[0];
    const float4* dists4 = (const float4*)d_in[1];
    const float4* rgb4   = (const float4*)d_in[2];
    const float*  bg     = (const float*) d_in[3];
    float*        out    = (float*)d_out;

    const int B = in_sizes[0] / 512;           // 65536 rays
    const int threads = 128;                    // 4 warps/block -> 8 rays/block
    const int blocks  = (B + 7) / 8;            // 8192 blocks

    nerf_composite_kernel<<<blocks, threads>>>(sigma4, dists4, rgb4, bg, out, B);
}

// round 16
// speedup vs baseline: 1.1281x; 1.1281x over previous
#include <cuda_runtime.h>

// NeRF volume rendering compositing — round 16: instruction diet on the
// R13 platform (12.58us; grid 8192 x 128, two rays/warp, 16-lane segments,
// 64-sample rounds, float4 default-cached loads, scan-predicated rgb,
// tau=1e-4). Changes (math-lean, structure identical):
//  1. dropped the +1e-10 on transmittance factors (<1e-8 relative effect);
//  2. weights as prefix-product differences: w_i*Tl = a_i - a_{i+1};
//  3. accW eliminated — sum of weights telescopes, so the background
//     remainder is exactly T_run at loop exit;
//  4. clip01 -> __saturatef (single instruction);
//  5. 3-accumulator reduction instead of 4.
// ~20% fewer issued instructions per lane; warm wall time has tracked
// instruction count across R11/R12/R14/R15.
// Inputs (metadata order):
//   d_in[0]: sigma  [B, S]    float32   (B=65536, S=512)
//   d_in[1]: dists  [B, S]    float32
//   d_in[2]: rgb    [B, S, 3] float32
//   d_in[3]: bg_col [3]       float32
// Output: rgb_map [B, 3] float32
//
//   x = sigma*dists*25; alpha = 1-exp(-x); T = excl cumprod(exp(-x))
//   w = alpha*T; out_c = sum w*sat(rgb) + T_end*bg_c
// Early termination at T < 1e-4: skipped mass telescopes into T_run and is
// composited as background; abs err < 1e-4, measured ~0.64*tau = 6.4e-5.

#define DIST_SCALE 25.0f
#define T_THRESH   1e-4f
#define FULLMASK   0xffffffffu
#define SEGW       16

__global__ __launch_bounds__(128, 16)
void nerf_composite_kernel(const float4* __restrict__ sigma4,
                           const float4* __restrict__ dists4,
                           const float4* __restrict__ rgb4,
                           const float*  __restrict__ bg,
                           float*        __restrict__ out,
                           int B)
{
    const int warp  = (int)((blockIdx.x * (unsigned)blockDim.x + threadIdx.x) >> 5);
    const int lane  = threadIdx.x & 31;
    const int slane = lane & (SEGW - 1);        // lane within 16-lane segment
    const int ray   = warp * 2 + (lane >> 4);   // one ray per half-warp
    if (ray >= B) return;

    float T_run = 1.0f;          // uniform within the segment
    float accR = 0.0f, accG = 0.0f, accB = 0.0f;

    // S = 512 samples = 8 rounds of 64 (4 samples/lane, float4 loads).
    #pragma unroll 1
    for (int k = 0; k < 8; ++k) {
        const int idx = ray * 128 + k * 16 + slane;   // float4 index into sigma/dists
        const float4 sg = sigma4[idx];
        const float4 dt = dists4[idx];

        // Transmittance factors f = exp(-sigma*dist*25); local prefix products.
        const float f0 = __expf(-DIST_SCALE * sg.x * dt.x);
        const float f1 = __expf(-DIST_SCALE * sg.y * dt.y);
        const float f2 = __expf(-DIST_SCALE * sg.z * dt.z);
        const float f3 = __expf(-DIST_SCALE * sg.w * dt.w);

        const float t2 = f0 * f1;        // prefix products within the lane
        const float t3 = t2 * f2;
        const float p  = t3 * f3;        // product of this lane's 4 factors

        // Segment (width-16) inclusive prefix product of p
        float incl = p;
        #pragma unroll
        for (int off = 1; off < SEGW; off <<= 1) {
            const float v = __shfl_up_sync(FULLMASK, incl, off, SEGW);
            if (slane >= off) incl *= v;
        }
        float excl = __shfl_up_sync(FULLMASK, incl, 1, SEGW);
        if (slane == 0) excl = 1.0f;
        const float total = __shfl_sync(FULLMASK, incl, SEGW - 1, SEGW);

        const float Tl = T_run * excl;   // transmittance at this lane's first sample

        // Lanes with negligible remaining transmittance skip rgb traffic.
        if (Tl >= T_THRESH) {
            const int ridx = ray * 384 + k * 48 + slane * 3;   // float4 index into rgb
            const float4 q0 = rgb4[ridx + 0];
            const float4 q1 = rgb4[ridx + 1];
            const float4 q2 = rgb4[ridx + 2];

            // Scaled transmittance ladder: a_i = Tl * prefix_i
            const float a1 = Tl * f0;
            const float a2 = Tl * t2;
            const float a3 = Tl * t3;
            const float a4 = Tl * p;
            const float w0 = Tl - a1;     // w_i * Tl, telescoped
            const float w1 = a1 - a2;
            const float w2 = a2 - a3;
            const float w3 = a3 - a4;

            accR += w0 * __saturatef(q0.x) + w1 * __saturatef(q0.w)
                  + w2 * __saturatef(q1.z) + w3 * __saturatef(q2.y);
            accG += w0 * __saturatef(q0.y) + w1 * __saturatef(q1.x)
                  + w2 * __saturatef(q1.w) + w3 * __saturatef(q2.z);
            accB += w0 * __saturatef(q0.z) + w1 * __saturatef(q1.y)
                  + w2 * __saturatef(q2.x) + w3 * __saturatef(q2.w);
        }

        T_run *= total;                          // stays segment-uniform
        const bool done = (T_run < T_THRESH);
        if (__all_sync(FULLMASK, done)) break;   // warp-uniform early exit
    }

    // Segment (width-16) reduction of the 3 color accumulators.
    #pragma unroll
    for (int off = SEGW / 2; off >= 1; off >>= 1) {
        accR += __shfl_down_sync(FULLMASK, accR, off, SEGW);
        accG += __shfl_down_sync(FULLMASK, accG, off, SEGW);
        accB += __shfl_down_sync(FULLMASK, accB, off, SEGW);
    }

    if (slane == 0) {
        // Background remainder telescopes exactly to the exit transmittance:
        // 1 - sum(processed w) = T_run. Skipped (sub-threshold) weight mass
        // stays inside T_run and is composited as background (abs err < tau).
        const float rem = T_run;
        out[ray * 3 + 0] = accR + rem * __ldg(&bg[0]);
        out[ray * 3 + 1] = accG + rem * __ldg(&bg[1]);
        out[ray * 3 + 2] = accB + rem * __ldg(&bg[2]);
    }
}

extern "C" void kernel_launch(void* const* d_in, const int* in_sizes, int n_in,
                              void* d_out, int out_size)
{
    const float4* sigma4 = (const float4*)d_in[0];
    const float4* dists4 = (const float4*)d_in[1];
    const float4* rgb4   = (const float4*)d_in[2];
    const float*  bg     = (const float*) d_in[3];
    float*        out    = (float*)d_out;

    const int B = in_sizes[0] / 512;           // 65536 rays
    const int threads = 128;                    // 4 warps/block -> 8 rays/block
    const int blocks  = (B + 7) / 8;            // 8192 blocks

    nerf_composite_kernel<<<blocks, threads>>>(sigma4, dists4, rgb4, bg, out, B);
}